// round 13
// baseline (speedup 1.0000x reference)
#include <cuda_runtime.h>
#include <cuda_bf16.h>
#include <cstdint>
#include <cstddef>

// ---------------------------------------------------------------------------
// HouseholderFlow via mma.sync (HMMA) — harness targets compute_103 (no 'a'),
// so tcgen05 is unavailable; optimize the legacy tensor path.
//   v0 = h_last @ W0^T + b0 ; z = HF(v0, z) ; then 7 more (Ws[j], bs[j]).
// GEMMs: bf16 3-term split (hi*hi + hi*lo + lo*hi), fp32 accumulate.
// K-space fused: 3 regions of 2048 -> one K=6144 chain per output tile.
// R12: 512 threads (16 warps, 4/SMSP) with 32x32 warp tiles for latency hiding.
// ---------------------------------------------------------------------------

#define B_DIM 8192
#define L_DIM 2048
#define NFLOW 8

#define BM 128
#define BN 128
#define BK 64                         // 64 bf16 = 128B rows (SW128 atom)
#define NTHR 512
#define STAGES 3
#define TILES (3 * (L_DIM / BK))      // 96
#define A_BYTES (BM * 128)            // 16384
#define B_BYTES (BN * 128)            // 16384
#define STAGE_BYTES (A_BYTES + B_BYTES)
#define SMEM_REQ (1024 + STAGES * STAGE_BYTES)

// ---- device scratch (allocation-free rule: static __device__ arrays) ----
__device__ __nv_bfloat16 g_Whi[(size_t)NFLOW * L_DIM * L_DIM];
__device__ __nv_bfloat16 g_Wlo[(size_t)NFLOW * L_DIM * L_DIM];
__device__ __nv_bfloat16 g_Ahi[2ull * B_DIM * L_DIM];
__device__ __nv_bfloat16 g_Alo[2ull * B_DIM * L_DIM];
__device__ float         g_z[(size_t)B_DIM * L_DIM];

// ---------------------------------------------------------------------------
__device__ __forceinline__ void split2(float x, __nv_bfloat16& h, __nv_bfloat16& l) {
    h = __float2bfloat16_rn(x);
    l = __float2bfloat16_rn(x - __bfloat162float(h));
}

__global__ void convert_split_kernel(const float4* __restrict__ src,
                                     __nv_bfloat16* __restrict__ hi,
                                     __nv_bfloat16* __restrict__ lo,
                                     int n4) {
    int i = blockIdx.x * blockDim.x + threadIdx.x;
    if (i >= n4) return;
    float4 x = src[i];
    __nv_bfloat16 h0, h1, h2, h3, l0, l1, l2, l3;
    split2(x.x, h0, l0); split2(x.y, h1, l1);
    split2(x.z, h2, l2); split2(x.w, h3, l3);
    __nv_bfloat162* H = reinterpret_cast<__nv_bfloat162*>(hi) + 2 * (size_t)i;
    __nv_bfloat162* L = reinterpret_cast<__nv_bfloat162*>(lo) + 2 * (size_t)i;
    H[0] = __halves2bfloat162(h0, h1);
    H[1] = __halves2bfloat162(h2, h3);
    L[0] = __halves2bfloat162(l0, l1);
    L[1] = __halves2bfloat162(l2, l3);
}

// SW128 swizzle on byte offsets (128B rows): chunk bits [4:6] ^= row bits [0:2]
__device__ __forceinline__ uint32_t sw128(uint32_t off) {
    return off ^ ((off >> 3) & 0x70);
}

// ---------------------------------------------------------------------------
// C[m,n] = sum_k A[m,k] * W[n,k] + bias[n]  (NT), K fused over 3 bf16 planes.
// 512 threads, warp grid 4x4, warp tile 32x32. 3-stage cp.async pipeline,
// register double-buffered ldmatrix fragments.
// ---------------------------------------------------------------------------
__global__ __launch_bounds__(NTHR, 1)
void gemm_hmma_kernel(const __nv_bfloat16* __restrict__ Ahi,
                      const __nv_bfloat16* __restrict__ Alo,
                      const __nv_bfloat16* __restrict__ Whi,
                      const __nv_bfloat16* __restrict__ Wlo,
                      const float* __restrict__ bias,
                      __nv_bfloat16* __restrict__ Ohi,
                      __nv_bfloat16* __restrict__ Olo) {
    extern __shared__ char smem[];
    const uint32_t sbase = (uint32_t)__cvta_generic_to_shared(smem);
    const uint32_t tile0 = (sbase + 1023u) & ~1023u;

    const int tid  = threadIdx.x;
    const int lane = tid & 31;
    const int warp = tid >> 5;
    const int wr   = warp >> 2;     // 0..3, 32 rows each
    const int wc   = warp & 3;      // 0..3, 32 cols each
    const int bm = blockIdx.y * BM;
    const int bn = blockIdx.x * BN;

    float acc[2][4][4];
#pragma unroll
    for (int mi = 0; mi < 2; mi++)
#pragma unroll
        for (int ni = 0; ni < 4; ni++)
#pragma unroll
            for (int e = 0; e < 4; e++) acc[mi][ni][e] = 0.f;

    auto load_tile = [&](int t) {
        const int s  = t % STAGES;
        const int r  = t >> 5;                 // 0=(Ahi,Whi) 1=(Ahi,Wlo) 2=(Alo,Whi)
        const int kk = (t & 31) << 6;          // k elem offset within region
        const __nv_bfloat16* Ap = (r < 2) ? Ahi : Alo;
        const __nv_bfloat16* Bp = (r == 1) ? Wlo : Whi;
        const uint32_t Ab = tile0 + s * STAGE_BYTES;
        const uint32_t Bb = Ab + A_BYTES;
#pragma unroll
        for (int i = 0; i < 2; i++) {          // A: 1024 x 16B chunks / 512 thr
            const int chunk = tid + i * NTHR;
            const int row = chunk >> 3;
            const int cb  = (chunk & 7) << 4;
            const uint32_t sw = sw128((uint32_t)(row * 128 + cb));
            const void* src = Ap + (size_t)(bm + row) * L_DIM + kk + (cb >> 1);
            asm volatile("cp.async.cg.shared.global [%0], [%1], 16;\n"
                         :: "r"(Ab + sw), "l"(src) : "memory");
        }
#pragma unroll
        for (int i = 0; i < 2; i++) {          // B: 1024 x 16B chunks / 512 thr
            const int chunk = tid + i * NTHR;
            const int row = chunk >> 3;
            const int cb  = (chunk & 7) << 4;
            const uint32_t sw = sw128((uint32_t)(row * 128 + cb));
            const void* src = Bp + (size_t)(bn + row) * L_DIM + kk + (cb >> 1);
            asm volatile("cp.async.cg.shared.global [%0], [%1], 16;\n"
                         :: "r"(Bb + sw), "l"(src) : "memory");
        }
        asm volatile("cp.async.commit_group;\n" ::: "memory");
    };

    // Per-warp fragment loads (ks = 0..3 selects 16-col sub-block of stage)
    const int arow = wr * 32 + (lane & 15);
    const int akb  = (lane >> 4) << 4;              // 0 or 16 bytes
    const int nrow = wc * 32 + ((lane >> 4) << 3) + (lane & 7);
    const int bkb  = ((lane >> 3) & 1) << 4;        // 0 or 16 bytes

    auto load_afrag = [&](uint32_t Ab, int ks, uint32_t a[2][4]) {
#pragma unroll
        for (int mi = 0; mi < 2; mi++) {
            const uint32_t off = (uint32_t)((arow + mi * 16) * 128 + ks * 32 + akb);
            const uint32_t addr = Ab + sw128(off);
            asm volatile(
                "ldmatrix.sync.aligned.m8n8.x4.shared.b16 {%0,%1,%2,%3}, [%4];"
                : "=r"(a[mi][0]), "=r"(a[mi][1]), "=r"(a[mi][2]), "=r"(a[mi][3])
                : "r"(addr));
        }
    };
    auto load_bfrag = [&](uint32_t Bb, int ks, uint32_t b[4][2]) {
#pragma unroll
        for (int nt = 0; nt < 2; nt++) {
            const uint32_t off = (uint32_t)((nrow + nt * 16) * 128 + ks * 32 + bkb);
            const uint32_t addr = Bb + sw128(off);
            asm volatile(
                "ldmatrix.sync.aligned.m8n8.x4.shared.b16 {%0,%1,%2,%3}, [%4];"
                : "=r"(b[2 * nt][0]), "=r"(b[2 * nt][1]),
                  "=r"(b[2 * nt + 1][0]), "=r"(b[2 * nt + 1][1])
                : "r"(addr));
        }
    };

    // Prologue: stages 0,1 in flight
    load_tile(0);
    load_tile(1);

    uint32_t afr[2][2][4], bfr[2][4][2];

    for (int t = 0; t < TILES; t++) {
        // Issue loads for t+2 (stage freed by last sync), then wait for group t.
        if (t + 2 < TILES) {
            load_tile(t + 2);
            asm volatile("cp.async.wait_group 2;\n" ::: "memory");
        } else if (t + 1 < TILES) {
            asm volatile("cp.async.wait_group 1;\n" ::: "memory");
        } else {
            asm volatile("cp.async.wait_group 0;\n" ::: "memory");
        }
        __syncthreads();

        const int s = t % STAGES;
        const uint32_t Ab = tile0 + s * STAGE_BYTES;
        const uint32_t Bb = Ab + A_BYTES;

        load_afrag(Ab, 0, afr[0]);
        load_bfrag(Bb, 0, bfr[0]);
#pragma unroll
        for (int ks = 0; ks < 4; ks++) {
            const int cur = ks & 1;
            if (ks < 3) {
                load_afrag(Ab, ks + 1, afr[cur ^ 1]);
                load_bfrag(Bb, ks + 1, bfr[cur ^ 1]);
            }
#pragma unroll
            for (int mi = 0; mi < 2; mi++)
#pragma unroll
                for (int ni = 0; ni < 4; ni++)
                    asm volatile(
                        "mma.sync.aligned.m16n8k16.row.col.f32.bf16.bf16.f32 "
                        "{%0,%1,%2,%3}, {%4,%5,%6,%7}, {%8,%9}, {%0,%1,%2,%3};"
                        : "+f"(acc[mi][ni][0]), "+f"(acc[mi][ni][1]),
                          "+f"(acc[mi][ni][2]), "+f"(acc[mi][ni][3])
                        : "r"(afr[cur][mi][0]), "r"(afr[cur][mi][1]),
                          "r"(afr[cur][mi][2]), "r"(afr[cur][mi][3]),
                          "r"(bfr[cur][ni][0]), "r"(bfr[cur][ni][1]));
        }
        __syncthreads();   // stage s reusable by the t+3 loads next iteration
    }

    // Epilogue: add bias, split into (hi, lo) bf16 planes.
    const int lr = lane >> 2;
    const int lc = (lane & 3) << 1;
#pragma unroll
    for (int mi = 0; mi < 2; mi++) {
#pragma unroll
        for (int ni = 0; ni < 4; ni++) {
            const int col = bn + wc * 32 + ni * 8 + lc;
            const float b0v = bias[col];
            const float b1v = bias[col + 1];
#pragma unroll
            for (int h = 0; h < 2; h++) {
                const int row = bm + wr * 32 + mi * 16 + lr + h * 8;
                const float x0 = acc[mi][ni][2 * h + 0] + b0v;
                const float x1 = acc[mi][ni][2 * h + 1] + b1v;
                __nv_bfloat16 h0, l0, h1, l1;
                split2(x0, h0, l0);
                split2(x1, h1, l1);
                const size_t off = (size_t)row * L_DIM + col;
                *reinterpret_cast<__nv_bfloat162*>(Ohi + off) = __halves2bfloat162(h0, h1);
                *reinterpret_cast<__nv_bfloat162*>(Olo + off) = __halves2bfloat162(l0, l1);
            }
        }
    }
}

// ---------------------------------------------------------------------------
// Householder reflection per row: z' = z - 2 v (v.z)/(v.v), v = hi + lo.
// ---------------------------------------------------------------------------
__global__ __launch_bounds__(256)
void reflect_kernel(const __nv_bfloat16* __restrict__ vhi,
                    const __nv_bfloat16* __restrict__ vlo,
                    const float* __restrict__ zin,
                    float* __restrict__ zout) {
    const int row = blockIdx.x;
    const int tid = threadIdx.x;
    const size_t base = (size_t)row * L_DIM;

    float v[8], z[8];
    float svz = 0.f, svv = 0.f;
#pragma unroll
    for (int i = 0; i < 8; i++) {
        const int c = tid + i * 256;
        const float vv = __bfloat162float(vhi[base + c]) + __bfloat162float(vlo[base + c]);
        const float zz = zin[base + c];
        v[i] = vv; z[i] = zz;
        svz += vv * zz;
        svv += vv * vv;
    }
#pragma unroll
    for (int o = 16; o > 0; o >>= 1) {
        svz += __shfl_xor_sync(0xFFFFFFFFu, svz, o);
        svv += __shfl_xor_sync(0xFFFFFFFFu, svv, o);
    }
    __shared__ float s[2][8];
    if ((tid & 31) == 0) {
        s[0][tid >> 5] = svz;
        s[1][tid >> 5] = svv;
    }
    __syncthreads();
    float tvz = 0.f, tvv = 0.f;
#pragma unroll
    for (int w = 0; w < 8; w++) { tvz += s[0][w]; tvv += s[1][w]; }
    const float scale = 2.f * tvz / tvv;
#pragma unroll
    for (int i = 0; i < 8; i++) {
        const int c = tid + i * 256;
        zout[base + c] = z[i] - scale * v[i];
    }
}

// ---------------------------------------------------------------------------
extern "C" void kernel_launch(void* const* d_in, const int* in_sizes, int n_in,
                              void* d_out, int out_size) {
    const float* z_in   = (const float*)d_in[0];   // [B, L]
    const float* h_last = (const float*)d_in[1];   // [B, H]
    const float* W0     = (const float*)d_in[2];   // [L, H]
    const float* b0     = (const float*)d_in[3];   // [L]
    const float* Ws     = (const float*)d_in[4];   // [NF-1, L, L]
    const float* bs     = (const float*)d_in[5];   // [NF-1, L]
    float* out          = (float*)d_out;           // [B, L]

    __nv_bfloat16 *Whi, *Wlo, *Ahi, *Alo;
    float* zb;
    cudaGetSymbolAddress((void**)&Whi, g_Whi);
    cudaGetSymbolAddress((void**)&Wlo, g_Wlo);
    cudaGetSymbolAddress((void**)&Ahi, g_Ahi);
    cudaGetSymbolAddress((void**)&Alo, g_Alo);
    cudaGetSymbolAddress((void**)&zb,  g_z);

    cudaFuncSetAttribute(gemm_hmma_kernel,
                         cudaFuncAttributeMaxDynamicSharedMemorySize, SMEM_REQ);

    const size_t WL = (size_t)L_DIM * L_DIM;
    const size_t PL = (size_t)B_DIM * L_DIM;

    // Split weights and h_last into bf16 hi/lo planes.
    {
        const int n4w0 = (int)(WL / 4);
        convert_split_kernel<<<(n4w0 + 255) / 256, 256>>>(
            (const float4*)W0, Whi, Wlo, n4w0);
        const int n4ws = (int)(7 * WL / 4);
        convert_split_kernel<<<(n4ws + 255) / 256, 256>>>(
            (const float4*)Ws, Whi + WL, Wlo + WL, n4ws);
        const int n4h = (int)(PL / 4);
        convert_split_kernel<<<(n4h + 255) / 256, 256>>>(
            (const float4*)h_last, Ahi, Alo, n4h);
    }

    dim3 gg(L_DIM / BN, B_DIM / BM);   // (16, 64)
    const float* zcur = z_in;
    int ping = 0;
    for (int j = 0; j < NFLOW; j++) {
        const __nv_bfloat16* ahi = Ahi + (size_t)ping * PL;
        const __nv_bfloat16* alo = Alo + (size_t)ping * PL;
        __nv_bfloat16* ohi = Ahi + (size_t)(ping ^ 1) * PL;
        __nv_bfloat16* olo = Alo + (size_t)(ping ^ 1) * PL;
        const float* bias = (j == 0) ? b0 : (bs + (size_t)(j - 1) * L_DIM);

        gemm_hmma_kernel<<<gg, NTHR, SMEM_REQ>>>(ahi, alo,
                                                 Whi + (size_t)j * WL,
                                                 Wlo + (size_t)j * WL,
                                                 bias, ohi, olo);

        float* zo = (j == NFLOW - 1) ? out : zb;
        reflect_kernel<<<B_DIM, 256>>>(ohi, olo, zcur, zo);

        zcur = zb;
        ping ^= 1;
    }
}

// round 14
// speedup vs baseline: 1.1595x; 1.1595x over previous
#include <cuda_runtime.h>
#include <cuda_bf16.h>
#include <cstdint>
#include <cstddef>

// ---------------------------------------------------------------------------
// HouseholderFlow via mma.sync (HMMA) — harness targets compute_103 (no 'a'),
// so tcgen05 is unavailable; optimize the legacy tensor path.
//   v0 = h_last @ W0^T + b0 ; z = HF(v0, z) ; then 7 more (Ws[j], bs[j]).
// GEMMs: bf16 3-term split (hi*hi + hi*lo + lo*hi), fp32 accumulate.
// K-space fused: 3 regions of 2048 -> one K=6144 chain per output tile.
// R13: BM=256 x BN=128 CTA tile, 64x64 warp tiles (4x2 grid, 256 thr) to
// halve smem fragment re-reads per MMA (LDS crossbar was co-binding).
// ---------------------------------------------------------------------------

#define B_DIM 8192
#define L_DIM 2048
#define NFLOW 8

#define BM 256
#define BN 128
#define BK 64                         // 64 bf16 = 128B rows (SW128 atom)
#define NTHR 256
#define STAGES 3
#define TILES (3 * (L_DIM / BK))      // 96
#define A_BYTES (BM * 128)            // 32768
#define B_BYTES (BN * 128)            // 16384
#define STAGE_BYTES (A_BYTES + B_BYTES)
#define SMEM_REQ (1024 + STAGES * STAGE_BYTES)   // ~145 KB

// ---- device scratch (allocation-free rule: static __device__ arrays) ----
__device__ __nv_bfloat16 g_Whi[(size_t)NFLOW * L_DIM * L_DIM];
__device__ __nv_bfloat16 g_Wlo[(size_t)NFLOW * L_DIM * L_DIM];
__device__ __nv_bfloat16 g_Ahi[2ull * B_DIM * L_DIM];
__device__ __nv_bfloat16 g_Alo[2ull * B_DIM * L_DIM];
__device__ float         g_z[(size_t)B_DIM * L_DIM];

// ---------------------------------------------------------------------------
__device__ __forceinline__ void split2(float x, __nv_bfloat16& h, __nv_bfloat16& l) {
    h = __float2bfloat16_rn(x);
    l = __float2bfloat16_rn(x - __bfloat162float(h));
}

__global__ void convert_split_kernel(const float4* __restrict__ src,
                                     __nv_bfloat16* __restrict__ hi,
                                     __nv_bfloat16* __restrict__ lo,
                                     int n4) {
    int i = blockIdx.x * blockDim.x + threadIdx.x;
    if (i >= n4) return;
    float4 x = src[i];
    __nv_bfloat16 h0, h1, h2, h3, l0, l1, l2, l3;
    split2(x.x, h0, l0); split2(x.y, h1, l1);
    split2(x.z, h2, l2); split2(x.w, h3, l3);
    __nv_bfloat162* H = reinterpret_cast<__nv_bfloat162*>(hi) + 2 * (size_t)i;
    __nv_bfloat162* L = reinterpret_cast<__nv_bfloat162*>(lo) + 2 * (size_t)i;
    H[0] = __halves2bfloat162(h0, h1);
    H[1] = __halves2bfloat162(h2, h3);
    L[0] = __halves2bfloat162(l0, l1);
    L[1] = __halves2bfloat162(l2, l3);
}

// SW128 swizzle on byte offsets (128B rows): chunk bits [4:6] ^= row bits [0:2]
__device__ __forceinline__ uint32_t sw128(uint32_t off) {
    return off ^ ((off >> 3) & 0x70);
}

// ---------------------------------------------------------------------------
// C[m,n] = sum_k A[m,k] * W[n,k] + bias[n]  (NT), K fused over 3 bf16 planes.
// 256 threads, warp grid 4(m) x 2(n), warp tile 64x64. 3-stage cp.async
// pipeline, register double-buffered ldmatrix fragments.
// ---------------------------------------------------------------------------
__global__ __launch_bounds__(NTHR, 1)
void gemm_hmma_kernel(const __nv_bfloat16* __restrict__ Ahi,
                      const __nv_bfloat16* __restrict__ Alo,
                      const __nv_bfloat16* __restrict__ Whi,
                      const __nv_bfloat16* __restrict__ Wlo,
                      const float* __restrict__ bias,
                      __nv_bfloat16* __restrict__ Ohi,
                      __nv_bfloat16* __restrict__ Olo) {
    extern __shared__ char smem[];
    const uint32_t sbase = (uint32_t)__cvta_generic_to_shared(smem);
    const uint32_t tile0 = (sbase + 1023u) & ~1023u;

    const int tid  = threadIdx.x;
    const int lane = tid & 31;
    const int warp = tid >> 5;
    const int wr   = warp >> 1;     // 0..3, 64 rows each
    const int wc   = warp & 1;      // 0..1, 64 cols each
    const int bm = blockIdx.y * BM;
    const int bn = blockIdx.x * BN;

    float acc[4][8][4];
#pragma unroll
    for (int mi = 0; mi < 4; mi++)
#pragma unroll
        for (int ni = 0; ni < 8; ni++)
#pragma unroll
            for (int e = 0; e < 4; e++) acc[mi][ni][e] = 0.f;

    auto load_tile = [&](int t) {
        const int s  = t % STAGES;
        const int r  = t >> 5;                 // 0=(Ahi,Whi) 1=(Ahi,Wlo) 2=(Alo,Whi)
        const int kk = (t & 31) << 6;          // k elem offset within region
        const __nv_bfloat16* Ap = (r < 2) ? Ahi : Alo;
        const __nv_bfloat16* Bp = (r == 1) ? Wlo : Whi;
        const uint32_t Ab = tile0 + s * STAGE_BYTES;
        const uint32_t Bb = Ab + A_BYTES;
#pragma unroll
        for (int i = 0; i < 8; i++) {          // A: 2048 x 16B chunks / 256 thr
            const int chunk = tid + i * NTHR;
            const int row = chunk >> 3;
            const int cb  = (chunk & 7) << 4;
            const uint32_t sw = sw128((uint32_t)(row * 128 + cb));
            const void* src = Ap + (size_t)(bm + row) * L_DIM + kk + (cb >> 1);
            asm volatile("cp.async.cg.shared.global [%0], [%1], 16;\n"
                         :: "r"(Ab + sw), "l"(src) : "memory");
        }
#pragma unroll
        for (int i = 0; i < 4; i++) {          // B: 1024 x 16B chunks / 256 thr
            const int chunk = tid + i * NTHR;
            const int row = chunk >> 3;
            const int cb  = (chunk & 7) << 4;
            const uint32_t sw = sw128((uint32_t)(row * 128 + cb));
            const void* src = Bp + (size_t)(bn + row) * L_DIM + kk + (cb >> 1);
            asm volatile("cp.async.cg.shared.global [%0], [%1], 16;\n"
                         :: "r"(Bb + sw), "l"(src) : "memory");
        }
        asm volatile("cp.async.commit_group;\n" ::: "memory");
    };

    // Per-warp fragment addressing (ks = 0..3 selects 16-col sub-block)
    const int arow = wr * 64 + (lane & 15);
    const int akb  = (lane >> 4) << 4;              // 0 or 16 bytes
    const int nrow = wc * 64 + ((lane >> 4) << 3) + (lane & 7);
    const int bkb  = ((lane >> 3) & 1) << 4;        // 0 or 16 bytes

    auto load_afrag = [&](uint32_t Ab, int ks, uint32_t a[4][4]) {
#pragma unroll
        for (int mi = 0; mi < 4; mi++) {
            const uint32_t off = (uint32_t)((arow + mi * 16) * 128 + ks * 32 + akb);
            const uint32_t addr = Ab + sw128(off);
            asm volatile(
                "ldmatrix.sync.aligned.m8n8.x4.shared.b16 {%0,%1,%2,%3}, [%4];"
                : "=r"(a[mi][0]), "=r"(a[mi][1]), "=r"(a[mi][2]), "=r"(a[mi][3])
                : "r"(addr));
        }
    };
    auto load_bfrag = [&](uint32_t Bb, int ks, uint32_t b[8][2]) {
#pragma unroll
        for (int nt = 0; nt < 4; nt++) {
            const uint32_t off = (uint32_t)((nrow + nt * 16) * 128 + ks * 32 + bkb);
            const uint32_t addr = Bb + sw128(off);
            asm volatile(
                "ldmatrix.sync.aligned.m8n8.x4.shared.b16 {%0,%1,%2,%3}, [%4];"
                : "=r"(b[2 * nt][0]), "=r"(b[2 * nt][1]),
                  "=r"(b[2 * nt + 1][0]), "=r"(b[2 * nt + 1][1])
                : "r"(addr));
        }
    };

    // Prologue: stages 0,1 in flight
    load_tile(0);
    load_tile(1);

    uint32_t afr[2][4][4], bfr[2][8][2];

    for (int t = 0; t < TILES; t++) {
        // Issue loads for t+2 (stage freed by last sync), then wait for group t.
        if (t + 2 < TILES) {
            load_tile(t + 2);
            asm volatile("cp.async.wait_group 2;\n" ::: "memory");
        } else if (t + 1 < TILES) {
            asm volatile("cp.async.wait_group 1;\n" ::: "memory");
        } else {
            asm volatile("cp.async.wait_group 0;\n" ::: "memory");
        }
        __syncthreads();

        const int s = t % STAGES;
        const uint32_t Ab = tile0 + s * STAGE_BYTES;
        const uint32_t Bb = Ab + A_BYTES;

        load_afrag(Ab, 0, afr[0]);
        load_bfrag(Bb, 0, bfr[0]);
#pragma unroll
        for (int ks = 0; ks < 4; ks++) {
            const int cur = ks & 1;
            if (ks < 3) {
                load_afrag(Ab, ks + 1, afr[cur ^ 1]);
                load_bfrag(Bb, ks + 1, bfr[cur ^ 1]);
            }
#pragma unroll
            for (int mi = 0; mi < 4; mi++)
#pragma unroll
                for (int ni = 0; ni < 8; ni++)
                    asm volatile(
                        "mma.sync.aligned.m16n8k16.row.col.f32.bf16.bf16.f32 "
                        "{%0,%1,%2,%3}, {%4,%5,%6,%7}, {%8,%9}, {%0,%1,%2,%3};"
                        : "+f"(acc[mi][ni][0]), "+f"(acc[mi][ni][1]),
                          "+f"(acc[mi][ni][2]), "+f"(acc[mi][ni][3])
                        : "r"(afr[cur][mi][0]), "r"(afr[cur][mi][1]),
                          "r"(afr[cur][mi][2]), "r"(afr[cur][mi][3]),
                          "r"(bfr[cur][ni][0]), "r"(bfr[cur][ni][1]));
        }
        __syncthreads();   // stage s reusable by the t+3 loads next iteration
    }

    // Epilogue: add bias, split into (hi, lo) bf16 planes.
    const int lr = lane >> 2;
    const int lc = (lane & 3) << 1;
#pragma unroll
    for (int mi = 0; mi < 4; mi++) {
#pragma unroll
        for (int ni = 0; ni < 8; ni++) {
            const int col = bn + wc * 64 + ni * 8 + lc;
            const float b0v = bias[col];
            const float b1v = bias[col + 1];
#pragma unroll
            for (int h = 0; h < 2; h++) {
                const int row = bm + wr * 64 + mi * 16 + lr + h * 8;
                const float x0 = acc[mi][ni][2 * h + 0] + b0v;
                const float x1 = acc[mi][ni][2 * h + 1] + b1v;
                __nv_bfloat16 h0, l0, h1, l1;
                split2(x0, h0, l0);
                split2(x1, h1, l1);
                const size_t off = (size_t)row * L_DIM + col;
                *reinterpret_cast<__nv_bfloat162*>(Ohi + off) = __halves2bfloat162(h0, h1);
                *reinterpret_cast<__nv_bfloat162*>(Olo + off) = __halves2bfloat162(l0, l1);
            }
        }
    }
}

// ---------------------------------------------------------------------------
// Householder reflection per row: z' = z - 2 v (v.z)/(v.v), v = hi + lo.
// ---------------------------------------------------------------------------
__global__ __launch_bounds__(256)
void reflect_kernel(const __nv_bfloat16* __restrict__ vhi,
                    const __nv_bfloat16* __restrict__ vlo,
                    const float* __restrict__ zin,
                    float* __restrict__ zout) {
    const int row = blockIdx.x;
    const int tid = threadIdx.x;
    const size_t base = (size_t)row * L_DIM;

    float v[8], z[8];
    float svz = 0.f, svv = 0.f;
#pragma unroll
    for (int i = 0; i < 8; i++) {
        const int c = tid + i * 256;
        const float vv = __bfloat162float(vhi[base + c]) + __bfloat162float(vlo[base + c]);
        const float zz = zin[base + c];
        v[i] = vv; z[i] = zz;
        svz += vv * zz;
        svv += vv * vv;
    }
#pragma unroll
    for (int o = 16; o > 0; o >>= 1) {
        svz += __shfl_xor_sync(0xFFFFFFFFu, svz, o);
        svv += __shfl_xor_sync(0xFFFFFFFFu, svv, o);
    }
    __shared__ float s[2][8];
    if ((tid & 31) == 0) {
        s[0][tid >> 5] = svz;
        s[1][tid >> 5] = svv;
    }
    __syncthreads();
    float tvz = 0.f, tvv = 0.f;
#pragma unroll
    for (int w = 0; w < 8; w++) { tvz += s[0][w]; tvv += s[1][w]; }
    const float scale = 2.f * tvz / tvv;
#pragma unroll
    for (int i = 0; i < 8; i++) {
        const int c = tid + i * 256;
        zout[base + c] = z[i] - scale * v[i];
    }
}

// ---------------------------------------------------------------------------
extern "C" void kernel_launch(void* const* d_in, const int* in_sizes, int n_in,
                              void* d_out, int out_size) {
    const float* z_in   = (const float*)d_in[0];   // [B, L]
    const float* h_last = (const float*)d_in[1];   // [B, H]
    const float* W0     = (const float*)d_in[2];   // [L, H]
    const float* b0     = (const float*)d_in[3];   // [L]
    const float* Ws     = (const float*)d_in[4];   // [NF-1, L, L]
    const float* bs     = (const float*)d_in[5];   // [NF-1, L]
    float* out          = (float*)d_out;           // [B, L]

    __nv_bfloat16 *Whi, *Wlo, *Ahi, *Alo;
    float* zb;
    cudaGetSymbolAddress((void**)&Whi, g_Whi);
    cudaGetSymbolAddress((void**)&Wlo, g_Wlo);
    cudaGetSymbolAddress((void**)&Ahi, g_Ahi);
    cudaGetSymbolAddress((void**)&Alo, g_Alo);
    cudaGetSymbolAddress((void**)&zb,  g_z);

    cudaFuncSetAttribute(gemm_hmma_kernel,
                         cudaFuncAttributeMaxDynamicSharedMemorySize, SMEM_REQ);

    const size_t WL = (size_t)L_DIM * L_DIM;
    const size_t PL = (size_t)B_DIM * L_DIM;

    // Split weights and h_last into bf16 hi/lo planes.
    {
        const int n4w0 = (int)(WL / 4);
        convert_split_kernel<<<(n4w0 + 255) / 256, 256>>>(
            (const float4*)W0, Whi, Wlo, n4w0);
        const int n4ws = (int)(7 * WL / 4);
        convert_split_kernel<<<(n4ws + 255) / 256, 256>>>(
            (const float4*)Ws, Whi + WL, Wlo + WL, n4ws);
        const int n4h = (int)(PL / 4);
        convert_split_kernel<<<(n4h + 255) / 256, 256>>>(
            (const float4*)h_last, Ahi, Alo, n4h);
    }

    dim3 gg(L_DIM / BN, B_DIM / BM);   // (16, 32)
    const float* zcur = z_in;
    int ping = 0;
    for (int j = 0; j < NFLOW; j++) {
        const __nv_bfloat16* ahi = Ahi + (size_t)ping * PL;
        const __nv_bfloat16* alo = Alo + (size_t)ping * PL;
        __nv_bfloat16* ohi = Ahi + (size_t)(ping ^ 1) * PL;
        __nv_bfloat16* olo = Alo + (size_t)(ping ^ 1) * PL;
        const float* bias = (j == 0) ? b0 : (bs + (size_t)(j - 1) * L_DIM);

        gemm_hmma_kernel<<<gg, NTHR, SMEM_REQ>>>(ahi, alo,
                                                 Whi + (size_t)j * WL,
                                                 Wlo + (size_t)j * WL,
                                                 bias, ohi, olo);

        float* zo = (j == NFLOW - 1) ? out : zb;
        reflect_kernel<<<B_DIM, 256>>>(ohi, olo, zcur, zo);

        zcur = zb;
        ping ^= 1;
    }
}

// round 17
// speedup vs baseline: 1.5100x; 1.3023x over previous
#include <cuda_runtime.h>
#include <cuda_bf16.h>
#include <cstdint>
#include <cstddef>

// ---------------------------------------------------------------------------
// HouseholderFlow via mma.sync (HMMA) — harness targets compute_103 (no 'a'),
// so tcgen05 is unavailable; optimize the legacy tensor path.
//   v0 = h_last @ W0^T + b0 ; z = HF(v0, z) ; then 7 more (Ws[j], bs[j]).
// GEMMs: bf16 3-term split (hi*hi + hi*lo + lo*hi), fp32 accumulate.
// K-space fused: 3 regions of 2048 -> one K=6144 chain per output tile.
// R14: 128 threads, 64x64 warp tiles (2x2), BM=BN=128, 2 CTAs/SM,
// CUTLASS-style single-sync mainloop with cross-tile fragment prefetch.
// ---------------------------------------------------------------------------

#define B_DIM 8192
#define L_DIM 2048
#define NFLOW 8

#define BM 128
#define BN 128
#define BK 64                         // 64 bf16 = 128B rows (SW128 atom)
#define NTHR 128
#define STAGES 3
#define TILES (3 * (L_DIM / BK))      // 96
#define A_BYTES (BM * 128)            // 16384
#define B_BYTES (BN * 128)            // 16384
#define STAGE_BYTES (A_BYTES + B_BYTES)
#define SMEM_REQ (1024 + STAGES * STAGE_BYTES)   // ~97 KB -> 2 CTAs/SM

// ---- device scratch (allocation-free rule: static __device__ arrays) ----
__device__ __nv_bfloat16 g_Whi[(size_t)NFLOW * L_DIM * L_DIM];
__device__ __nv_bfloat16 g_Wlo[(size_t)NFLOW * L_DIM * L_DIM];
__device__ __nv_bfloat16 g_Ahi[2ull * B_DIM * L_DIM];
__device__ __nv_bfloat16 g_Alo[2ull * B_DIM * L_DIM];
__device__ float         g_z[(size_t)B_DIM * L_DIM];

// ---------------------------------------------------------------------------
__device__ __forceinline__ void split2(float x, __nv_bfloat16& h, __nv_bfloat16& l) {
    h = __float2bfloat16_rn(x);
    l = __float2bfloat16_rn(x - __bfloat162float(h));
}

__global__ void convert_split_kernel(const float4* __restrict__ src,
                                     __nv_bfloat16* __restrict__ hi,
                                     __nv_bfloat16* __restrict__ lo,
                                     int n4) {
    int i = blockIdx.x * blockDim.x + threadIdx.x;
    if (i >= n4) return;
    float4 x = src[i];
    __nv_bfloat16 h0, h1, h2, h3, l0, l1, l2, l3;
    split2(x.x, h0, l0); split2(x.y, h1, l1);
    split2(x.z, h2, l2); split2(x.w, h3, l3);
    __nv_bfloat162* H = reinterpret_cast<__nv_bfloat162*>(hi) + 2 * (size_t)i;
    __nv_bfloat162* L = reinterpret_cast<__nv_bfloat162*>(lo) + 2 * (size_t)i;
    H[0] = __halves2bfloat162(h0, h1);
    H[1] = __halves2bfloat162(h2, h3);
    L[0] = __halves2bfloat162(l0, l1);
    L[1] = __halves2bfloat162(l2, l3);
}

// SW128 swizzle on byte offsets (128B rows): chunk bits [4:6] ^= row bits [0:2]
__device__ __forceinline__ uint32_t sw128(uint32_t off) {
    return off ^ ((off >> 3) & 0x70);
}

// ---------------------------------------------------------------------------
// C[m,n] = sum_k A[m,k] * W[n,k] + bias[n]  (NT), K fused over 3 bf16 planes.
// 128 threads, warp grid 2x2, warp tile 64x64. Single __syncthreads per
// k-tile; next tile's ks0 fragments prefetched under the ks3 MMA burst.
// ---------------------------------------------------------------------------
__global__ __launch_bounds__(NTHR, 2)
void gemm_hmma_kernel(const __nv_bfloat16* __restrict__ Ahi,
                      const __nv_bfloat16* __restrict__ Alo,
                      const __nv_bfloat16* __restrict__ Whi,
                      const __nv_bfloat16* __restrict__ Wlo,
                      const float* __restrict__ bias,
                      __nv_bfloat16* __restrict__ Ohi,
                      __nv_bfloat16* __restrict__ Olo) {
    extern __shared__ char smem[];
    const uint32_t sbase = (uint32_t)__cvta_generic_to_shared(smem);
    const uint32_t tile0 = (sbase + 1023u) & ~1023u;

    const int tid  = threadIdx.x;
    const int lane = tid & 31;
    const int warp = tid >> 5;
    const int wr   = warp >> 1;     // 0..1, 64 rows each
    const int wc   = warp & 1;      // 0..1, 64 cols each
    const int bm = blockIdx.y * BM;
    const int bn = blockIdx.x * BN;

    float acc[4][8][4];
#pragma unroll
    for (int mi = 0; mi < 4; mi++)
#pragma unroll
        for (int ni = 0; ni < 8; ni++)
#pragma unroll
            for (int e = 0; e < 4; e++) acc[mi][ni][e] = 0.f;

    auto load_tile = [&](int t) {
        const int s  = t % STAGES;
        const int r  = t >> 5;                 // 0=(Ahi,Whi) 1=(Ahi,Wlo) 2=(Alo,Whi)
        const int kk = (t & 31) << 6;          // k elem offset within region
        const __nv_bfloat16* Ap = (r < 2) ? Ahi : Alo;
        const __nv_bfloat16* Bp = (r == 1) ? Wlo : Whi;
        const uint32_t Ab = tile0 + s * STAGE_BYTES;
        const uint32_t Bb = Ab + A_BYTES;
#pragma unroll
        for (int i = 0; i < 8; i++) {          // A: 1024 x 16B chunks / 128 thr
            const int chunk = tid + i * NTHR;
            const int row = chunk >> 3;
            const int cb  = (chunk & 7) << 4;
            const uint32_t sw = sw128((uint32_t)(row * 128 + cb));
            const void* src = Ap + (size_t)(bm + row) * L_DIM + kk + (cb >> 1);
            asm volatile("cp.async.cg.shared.global [%0], [%1], 16;\n"
                         :: "r"(Ab + sw), "l"(src) : "memory");
        }
#pragma unroll
        for (int i = 0; i < 8; i++) {          // B: 1024 x 16B chunks / 128 thr
            const int chunk = tid + i * NTHR;
            const int row = chunk >> 3;
            const int cb  = (chunk & 7) << 4;
            const uint32_t sw = sw128((uint32_t)(row * 128 + cb));
            const void* src = Bp + (size_t)(bn + row) * L_DIM + kk + (cb >> 1);
            asm volatile("cp.async.cg.shared.global [%0], [%1], 16;\n"
                         :: "r"(Bb + sw), "l"(src) : "memory");
        }
        asm volatile("cp.async.commit_group;\n" ::: "memory");
    };

    // Per-warp fragment addressing (ks = 0..3 selects 16-col sub-block)
    const int arow = wr * 64 + (lane & 15);
    const int akb  = (lane >> 4) << 4;              // 0 or 16 bytes
    const int nrow = wc * 64 + ((lane >> 4) << 3) + (lane & 7);
    const int bkb  = ((lane >> 3) & 1) << 4;        // 0 or 16 bytes

    auto load_afrag = [&](uint32_t Ab, int ks, uint32_t a[4][4]) {
#pragma unroll
        for (int mi = 0; mi < 4; mi++) {
            const uint32_t off = (uint32_t)((arow + mi * 16) * 128 + ks * 32 + akb);
            const uint32_t addr = Ab + sw128(off);
            asm volatile(
                "ldmatrix.sync.aligned.m8n8.x4.shared.b16 {%0,%1,%2,%3}, [%4];"
                : "=r"(a[mi][0]), "=r"(a[mi][1]), "=r"(a[mi][2]), "=r"(a[mi][3])
                : "r"(addr));
        }
    };
    auto load_bfrag = [&](uint32_t Bb, int ks, uint32_t b[8][2]) {
#pragma unroll
        for (int nt = 0; nt < 4; nt++) {
            const uint32_t off = (uint32_t)((nrow + nt * 16) * 128 + ks * 32 + bkb);
            const uint32_t addr = Bb + sw128(off);
            asm volatile(
                "ldmatrix.sync.aligned.m8n8.x4.shared.b16 {%0,%1,%2,%3}, [%4];"
                : "=r"(b[2 * nt][0]), "=r"(b[2 * nt][1]),
                  "=r"(b[2 * nt + 1][0]), "=r"(b[2 * nt + 1][1])
                : "r"(addr));
        }
    };

    // Prologue: stages 0,1 in flight; wait stage 0, load its ks0 fragments.
    load_tile(0);
    load_tile(1);
    asm volatile("cp.async.wait_group 1;\n" ::: "memory");
    __syncthreads();

    uint32_t afr[2][4][4], bfr[2][8][2];
    {
        const uint32_t Ab = tile0;
        load_afrag(Ab, 0, afr[0]);
        load_bfrag(Ab + A_BYTES, 0, bfr[0]);
    }

    for (int t = 0; t < TILES; t++) {
        const int s = t % STAGES;
        const uint32_t Ab = tile0 + s * STAGE_BYTES;
        const uint32_t Bb = Ab + A_BYTES;

        // Issue next-next tile loads; writes stage (t-1)%3, whose smem reads
        // all precede the single barrier of tile t-1 (CUTLASS multistage rule).
        if (t + 2 < TILES) load_tile(t + 2);

#pragma unroll
        for (int ks = 0; ks < 4; ks++) {
            const int cur = ks & 1;
            if (ks < 3) {
                load_afrag(Ab, ks + 1, afr[cur ^ 1]);
                load_bfrag(Bb, ks + 1, bfr[cur ^ 1]);
            } else if (t + 1 < TILES) {
                // Make tile t+1's stage visible, then prefetch its ks0 frags;
                // the ks3 MMA burst below covers barrier exit + LDSM latency.
                if (t + 2 < TILES) {
                    asm volatile("cp.async.wait_group 1;\n" ::: "memory");
                } else {
                    asm volatile("cp.async.wait_group 0;\n" ::: "memory");
                }
                __syncthreads();
                const uint32_t An = tile0 + ((t + 1) % STAGES) * STAGE_BYTES;
                load_afrag(An, 0, afr[cur ^ 1]);
                load_bfrag(An + A_BYTES, 0, bfr[cur ^ 1]);
            }
#pragma unroll
            for (int mi = 0; mi < 4; mi++)
#pragma unroll
                for (int ni = 0; ni < 8; ni++)
                    asm volatile(
                        "mma.sync.aligned.m16n8k16.row.col.f32.bf16.bf16.f32 "
                        "{%0,%1,%2,%3}, {%4,%5,%6,%7}, {%8,%9}, {%0,%1,%2,%3};"
                        : "+f"(acc[mi][ni][0]), "+f"(acc[mi][ni][1]),
                          "+f"(acc[mi][ni][2]), "+f"(acc[mi][ni][3])
                        : "r"(afr[cur][mi][0]), "r"(afr[cur][mi][1]),
                          "r"(afr[cur][mi][2]), "r"(afr[cur][mi][3]),
                          "r"(bfr[cur][ni][0]), "r"(bfr[cur][ni][1]));
        }
    }

    // Epilogue: add bias, split into (hi, lo) bf16 planes.
    const int lr = lane >> 2;
    const int lc = (lane & 3) << 1;
#pragma unroll
    for (int mi = 0; mi < 4; mi++) {
#pragma unroll
        for (int ni = 0; ni < 8; ni++) {
            const int col = bn + wc * 64 + ni * 8 + lc;
            const float b0v = bias[col];
            const float b1v = bias[col + 1];
#pragma unroll
            for (int h = 0; h < 2; h++) {
                const int row = bm + wr * 64 + mi * 16 + lr + h * 8;
                const float x0 = acc[mi][ni][2 * h + 0] + b0v;
                const float x1 = acc[mi][ni][2 * h + 1] + b1v;
                __nv_bfloat16 h0, l0, h1, l1;
                split2(x0, h0, l0);
                split2(x1, h1, l1);
                const size_t off = (size_t)row * L_DIM + col;
                *reinterpret_cast<__nv_bfloat162*>(Ohi + off) = __halves2bfloat162(h0, h1);
                *reinterpret_cast<__nv_bfloat162*>(Olo + off) = __halves2bfloat162(l0, l1);
            }
        }
    }
}

// ---------------------------------------------------------------------------
// Householder reflection per row: z' = z - 2 v (v.z)/(v.v), v = hi + lo.
// ---------------------------------------------------------------------------
__global__ __launch_bounds__(256)
void reflect_kernel(const __nv_bfloat16* __restrict__ vhi,
                    const __nv_bfloat16* __restrict__ vlo,
                    const float* __restrict__ zin,
                    float* __restrict__ zout) {
    const int row = blockIdx.x;
    const int tid = threadIdx.x;
    const size_t base = (size_t)row * L_DIM;

    float v[8], z[8];
    float svz = 0.f, svv = 0.f;
#pragma unroll
    for (int i = 0; i < 8; i++) {
        const int c = tid + i * 256;
        const float vv = __bfloat162float(vhi[base + c]) + __bfloat162float(vlo[base + c]);
        const float zz = zin[base + c];
        v[i] = vv; z[i] = zz;
        svz += vv * zz;
        svv += vv * vv;
    }
#pragma unroll
    for (int o = 16; o > 0; o >>= 1) {
        svz += __shfl_xor_sync(0xFFFFFFFFu, svz, o);
        svv += __shfl_xor_sync(0xFFFFFFFFu, svv, o);
    }
    __shared__ float s[2][8];
    if ((tid & 31) == 0) {
        s[0][tid >> 5] = svz;
        s[1][tid >> 5] = svv;
    }
    __syncthreads();
    float tvz = 0.f, tvv = 0.f;
#pragma unroll
    for (int w = 0; w < 8; w++) { tvz += s[0][w]; tvv += s[1][w]; }
    const float scale = 2.f * tvz / tvv;
#pragma unroll
    for (int i = 0; i < 8; i++) {
        const int c = tid + i * 256;
        zout[base + c] = z[i] - scale * v[i];
    }
}

// ---------------------------------------------------------------------------
extern "C" void kernel_launch(void* const* d_in, const int* in_sizes, int n_in,
                              void* d_out, int out_size) {
    const float* z_in   = (const float*)d_in[0];   // [B, L]
    const float* h_last = (const float*)d_in[1];   // [B, H]
    const float* W0     = (const float*)d_in[2];   // [L, H]
    const float* b0     = (const float*)d_in[3];   // [L]
    const float* Ws     = (const float*)d_in[4];   // [NF-1, L, L]
    const float* bs     = (const float*)d_in[5];   // [NF-1, L]
    float* out          = (float*)d_out;           // [B, L]

    __nv_bfloat16 *Whi, *Wlo, *Ahi, *Alo;
    float* zb;
    cudaGetSymbolAddress((void**)&Whi, g_Whi);
    cudaGetSymbolAddress((void**)&Wlo, g_Wlo);
    cudaGetSymbolAddress((void**)&Ahi, g_Ahi);
    cudaGetSymbolAddress((void**)&Alo, g_Alo);
    cudaGetSymbolAddress((void**)&zb,  g_z);

    cudaFuncSetAttribute(gemm_hmma_kernel,
                         cudaFuncAttributeMaxDynamicSharedMemorySize, SMEM_REQ);

    const size_t WL = (size_t)L_DIM * L_DIM;
    const size_t PL = (size_t)B_DIM * L_DIM;

    // Split weights and h_last into bf16 hi/lo planes.
    {
        const int n4w0 = (int)(WL / 4);
        convert_split_kernel<<<(n4w0 + 255) / 256, 256>>>(
            (const float4*)W0, Whi, Wlo, n4w0);
        const int n4ws = (int)(7 * WL / 4);
        convert_split_kernel<<<(n4ws + 255) / 256, 256>>>(
            (const float4*)Ws, Whi + WL, Wlo + WL, n4ws);
        const int n4h = (int)(PL / 4);
        convert_split_kernel<<<(n4h + 255) / 256, 256>>>(
            (const float4*)h_last, Ahi, Alo, n4h);
    }

    dim3 gg(L_DIM / BN, B_DIM / BM);   // (16, 64) = 1024 CTAs
    const float* zcur = z_in;
    int ping = 0;
    for (int j = 0; j < NFLOW; j++) {
        const __nv_bfloat16* ahi = Ahi + (size_t)ping * PL;
        const __nv_bfloat16* alo = Alo + (size_t)ping * PL;
        __nv_bfloat16* ohi = Ahi + (size_t)(ping ^ 1) * PL;
        __nv_bfloat16* olo = Alo + (size_t)(ping ^ 1) * PL;
        const float* bias = (j == 0) ? b0 : (bs + (size_t)(j - 1) * L_DIM);

        gemm_hmma_kernel<<<gg, NTHR, SMEM_REQ>>>(ahi, alo,
                                                 Whi + (size_t)j * WL,
                                                 Wlo + (size_t)j * WL,
                                                 bias, ohi, olo);

        float* zo = (j == NFLOW - 1) ? out : zb;
        reflect_kernel<<<B_DIM, 256>>>(ohi, olo, zcur, zo);

        zcur = zb;
        ping ^= 1;
    }
}